// round 9
// baseline (speedup 1.0000x reference)
#include <cuda_runtime.h>

typedef unsigned long long ull;

// ---- packed f32x2 helpers ----
__device__ __forceinline__ ull pk2(float lo, float hi) {
    ull r; asm("mov.b64 %0, {%1, %2};" : "=l"(r) : "f"(lo), "f"(hi)); return r;
}
__device__ __forceinline__ ull bc2(float v) { return pk2(v, v); }
__device__ __forceinline__ void upk2(ull r, float& lo, float& hi) {
    asm("mov.b64 {%0, %1}, %2;" : "=f"(lo), "=f"(hi) : "l"(r));
}
__device__ __forceinline__ ull fma2(ull a, ull b, ull c) {
    ull d; asm("fma.rn.f32x2 %0, %1, %2, %3;" : "=l"(d) : "l"(a), "l"(b), "l"(c)); return d;
}
__device__ __forceinline__ ull add2(ull a, ull b) {
    ull d; asm("add.rn.f32x2 %0, %1, %2;" : "=l"(d) : "l"(a), "l"(b)); return d;
}
__device__ __forceinline__ ull mul2(ull a, ull b) {
    ull d; asm("mul.rn.f32x2 %0, %1, %2;" : "=l"(d) : "l"(a), "l"(b)); return d;
}
__device__ __forceinline__ float ex2a(float x) {
    float y; asm("ex2.approx.f32 %0, %1;" : "=f"(y) : "f"(x)); return y;
}
__device__ __forceinline__ float rcpa(float x) {
    float y; asm("rcp.approx.f32 %0, %1;" : "=f"(y) : "f"(x)); return y;
}

// Shapes: b=4, c=16, m=8, h=w=64, O=64.
// CTA: 256 threads = jh(2) x sp(4) x ol(32); covers o-half oh = blockIdx.x&1.
// 2 CTAs resident per SM (prologue of one overlaps main loop of the other).
// Smem (floats):
//   qs  [0,8256)       q[i][ol*16+pix], i-stride 516
//   xs  [8256,10368)   x[ch][m*16+pix], ch-stride 132
//   res [10368,10624)  0.125*sum_m x, [i*16+pix]
//   wqs [10624,10880)  wq(this half) * 0.125*log2(e), [ol*8+m]
//   wkp [10880,11456)  ull j-pairs [r2*9+m], rows (2r2,2r2+1), all 64
//   wvp [11456,12032)  same for wv
#define QS_I 516
#define XS_CH 132
#define SMEM_FLOATS 12032
#define SMEM_BYTES (SMEM_FLOATS * 4)

__global__ __launch_bounds__(256, 2) void adapt_attn(
    const float* __restrict__ x,
    const float* __restrict__ wq,
    const float* __restrict__ wk,
    const float* __restrict__ wv,
    float* __restrict__ out)
{
    extern __shared__ __align__(16) float smem[];
    float* qs  = smem;
    float* xs  = smem + 8256;
    float* res = smem + 10368;
    float* wqs = smem + 10624;
    ull*   wkp = (ull*)(smem + 10880);
    ull*   wvp = (ull*)(smem + 11456);

    const int t   = threadIdx.x;
    const int bx  = blockIdx.x;   // 0..15
    const int lwg = bx >> 1;      // 0..7
    const int oh  = bx & 1;       // o-half
    const int lh  = blockIdx.y;   // 0..31
    const int b   = blockIdx.z;   // 0..3
    const int hh0 = 2 * lh, ww0 = 8 * lwg;

    // ---- stage x tile (512 float4): pix = sp*4 + (hhi*2 + colbit) ----
#pragma unroll
    for (int it = 0; it < 2; ++it) {
        int idx = t + it * 256;
        int q4  = idx & 1;
        int hhi = (idx >> 1) & 1;
        int m   = (idx >> 2) & 7;
        int ch  = idx >> 5;
        const float4 v = *reinterpret_cast<const float4*>(
            x + ((b * 16 + ch) * 8 + m) * 4096 + (hh0 + hhi) * 64 + ww0 + 4 * q4);
        float* dst = xs + ch * XS_CH + m * 16 + 8 * q4 + 2 * hhi;
        *reinterpret_cast<ull*>(dst)     = pk2(v.x, v.y);
        *reinterpret_cast<ull*>(dst + 4) = pk2(v.z, v.w);
    }
    // ---- stage weights ----
    {
        int m = t & 7, r = t >> 3;                       // r = ol 0..31
        wqs[t] = wq[(oh * 32 + r) * 8 + m] * 0.18033688011112042f;  // 0.125*log2e
        // r doubles as r2 index (rows 2r, 2r+1) for k/v pairs
        wkp[r * 9 + m] = pk2(wk[(2 * r) * 8 + m], wk[(2 * r + 1) * 8 + m]);
        wvp[r * 9 + m] = pk2(wv[(2 * r) * 8 + m], wv[(2 * r + 1) * 8 + m]);
    }
    __syncthreads();

    // ---- res = 0.125 * sum_m x ----
    {
        int i = t >> 4, pix = t & 15;
        const float* xr = xs + i * XS_CH + pix;
        float s = 0.f;
#pragma unroll
        for (int m = 0; m < 8; ++m) s += xr[m * 16];
        res[i * 16 + pix] = 0.125f * s;
    }

    // ---- cooperative q (loop-interchanged): i = t&15, og = t>>4 -> 2 ol ----
    {
        int i = t & 15, og = t >> 4;
        const ull* xr = reinterpret_cast<const ull*>(xs + i * XS_CH);
        const float* wo = wqs + (og * 2) * 8;
        ull acc[2][8];
#pragma unroll
        for (int n = 0; n < 2; ++n)
#pragma unroll
            for (int p = 0; p < 8; ++p) acc[n][p] = 0ull;
#pragma unroll
        for (int m = 0; m < 8; ++m) {
            ull xm[8];
#pragma unroll
            for (int p = 0; p < 8; ++p) xm[p] = xr[m * 8 + p];
#pragma unroll
            for (int n = 0; n < 2; ++n) {
                ull wb = bc2(wo[n * 8 + m]);
#pragma unroll
                for (int p = 0; p < 8; ++p)
                    acc[n][p] = fma2(wb, xm[p], acc[n][p]);
            }
        }
#pragma unroll
        for (int n = 0; n < 2; ++n) {
            ull* qd = reinterpret_cast<ull*>(qs + i * QS_I + (og * 2 + n) * 16);
#pragma unroll
            for (int p = 0; p < 8; ++p) qd[p] = acc[n][p];
        }
    }

    // ---- per-thread k/v for its (ol, jh) half: 8 j as 4 pairs ----
    const int jh = t & 1;
    const int sp = (t >> 1) & 3;
    const int ol = t >> 3;                 // 0..31
    const int o  = oh * 32 + ol;           // global o
    const int ck = o >> 2;                 // x channel 0..15

    ull kq[4][4], vq[4][4];
#pragma unroll
    for (int j2 = 0; j2 < 4; ++j2)
#pragma unroll
        for (int p = 0; p < 4; ++p) { kq[j2][p] = 0ull; vq[j2][p] = 0ull; }
    {
        const int r2b = (ol & 3) * 8 + jh * 4;          // 4 row-pairs
        const ull* wkg = wkp + r2b * 9;
        const ull* wvg = wvp + r2b * 9;
        const float* xck = xs + ck * XS_CH;
#pragma unroll
        for (int m = 0; m < 8; ++m) {
            float4 xv = *reinterpret_cast<const float4*>(xck + m * 16 + sp * 4);
            ull xb0 = bc2(xv.x), xb1 = bc2(xv.y), xb2 = bc2(xv.z), xb3 = bc2(xv.w);
#pragma unroll
            for (int j2 = 0; j2 < 4; ++j2) {
                ull wkv = wkg[j2 * 9 + m];
                kq[j2][0] = fma2(wkv, xb0, kq[j2][0]);
                kq[j2][1] = fma2(wkv, xb1, kq[j2][1]);
                kq[j2][2] = fma2(wkv, xb2, kq[j2][2]);
                kq[j2][3] = fma2(wkv, xb3, kq[j2][3]);
                ull wvv = wvg[j2 * 9 + m];
                vq[j2][0] = fma2(wvv, xb0, vq[j2][0]);
                vq[j2][1] = fma2(wvv, xb1, vq[j2][1]);
                vq[j2][2] = fma2(wvv, xb2, vq[j2][2]);
                vq[j2][3] = fma2(wvv, xb3, vq[j2][3]);
            }
        }
    }
    __syncthreads();   // qs/res complete before main loop

    const float* qso  = qs + ol * 16 + sp * 4;
    const ull*   resp = reinterpret_cast<const ull*>(res) + sp * 2 + jh;
    float* op = out + ((b * 16) * 64 + o) * 4096 + (hh0 + jh) * 64 + ww0 + 2 * sp;

    // ==== main loop with q software prefetch ====
    float4 qv = *reinterpret_cast<const float4*>(qso);
#pragma unroll 1
    for (int i = 0; i < 16; ++i) {
        float4 qvn = *reinterpret_cast<const float4*>(qso + ((i + 1) & 15) * QS_I);

        ull qb0 = bc2(qv.x), qb1 = bc2(qv.y), qb2 = bc2(qv.z), qb3 = bc2(qv.w);

        // att (pre-scaled) -> e = 2^att, this thread's 8 j as 4 pairs
        ull ep[4];
#pragma unroll
        for (int j2 = 0; j2 < 4; ++j2) {
            ull at = mul2(qb0, kq[j2][0]);
            at = fma2(qb1, kq[j2][1], at);
            at = fma2(qb2, kq[j2][2], at);
            at = fma2(qb3, kq[j2][3], at);
            float alo, ahi; upk2(at, alo, ahi);
            ep[j2] = pk2(ex2a(alo), ex2a(ahi));
        }

        // softmax denominator: local 8 + butterfly over jh
        ull s2 = add2(add2(ep[0], ep[1]), add2(ep[2], ep[3]));
        float slo, shi; upk2(s2, slo, shi);
        float fs = slo + shi;
        fs += __shfl_xor_sync(0xffffffffu, fs, 1);
        ull invb = bc2(rcpa(fs));

        // out partial over this j-half
        ull a0 = mul2(ep[0], vq[0][0]);
        ull a1 = mul2(ep[0], vq[0][1]);
        ull a2 = mul2(ep[0], vq[0][2]);
        ull a3 = mul2(ep[0], vq[0][3]);
#pragma unroll
        for (int j2 = 1; j2 < 4; ++j2) {
            a0 = fma2(ep[j2], vq[j2][0], a0);
            a1 = fma2(ep[j2], vq[j2][1], a1);
            a2 = fma2(ep[j2], vq[j2][2], a2);
            a3 = fma2(ep[j2], vq[j2][3], a3);
        }
        float e0, e1, e2, e3, d0, d1, d2, d3;
        upk2(a0, e0, d0); upk2(a1, e1, d1);
        upk2(a2, e2, d2); upk2(a3, e3, d3);
        ull mineA = pk2(e0 + d0, e1 + d1);   // row hh0   cols (2sp, 2sp+1)
        ull mineB = pk2(e2 + d2, e3 + d3);   // row hh0+1 cols (2sp, 2sp+1)

        // exchange j-halves: jh=0 finalizes row hh0, jh=1 row hh0+1
        ull keep = jh ? mineB : mineA;
        ull send = jh ? mineA : mineB;
        ull recv = __shfl_xor_sync(0xffffffffu, send, 1);
        ull fin  = fma2(add2(keep, recv), invb, resp[i * 8]);
        *reinterpret_cast<ull*>(op) = fin;
        op += 64 * 4096;

        qv = qvn;
    }
}

extern "C" void kernel_launch(void* const* d_in, const int* in_sizes, int n_in,
                              void* d_out, int out_size) {
    const float* x  = (const float*)d_in[0];
    const float* wq = (const float*)d_in[1];
    const float* wk = (const float*)d_in[2];
    const float* wv = (const float*)d_in[3];
    // d_in[4] (w_p): positional term is constant over the softmax axis -> cancels exactly.
    static int attr_set = 0;
    if (!attr_set) {
        cudaFuncSetAttribute(adapt_attn, cudaFuncAttributeMaxDynamicSharedMemorySize,
                             SMEM_BYTES);
        attr_set = 1;
    }
    dim3 grid(16, 32, 4);   // (lwg*2+oh, lh, b)
    adapt_attn<<<grid, 256, SMEM_BYTES>>>(x, wq, wk, wv, (float*)d_out);
}

// round 10
// speedup vs baseline: 1.1361x; 1.1361x over previous
#include <cuda_runtime.h>

typedef unsigned long long ull;

// ---- packed f32x2 helpers ----
__device__ __forceinline__ ull pk2(float lo, float hi) {
    ull r; asm("mov.b64 %0, {%1, %2};" : "=l"(r) : "f"(lo), "f"(hi)); return r;
}
__device__ __forceinline__ ull bc2(float v) { return pk2(v, v); }
__device__ __forceinline__ void upk2(ull r, float& lo, float& hi) {
    asm("mov.b64 {%0, %1}, %2;" : "=f"(lo), "=f"(hi) : "l"(r));
}
__device__ __forceinline__ ull fma2(ull a, ull b, ull c) {
    ull d; asm("fma.rn.f32x2 %0, %1, %2, %3;" : "=l"(d) : "l"(a), "l"(b), "l"(c)); return d;
}
__device__ __forceinline__ ull add2(ull a, ull b) {
    ull d; asm("add.rn.f32x2 %0, %1, %2;" : "=l"(d) : "l"(a), "l"(b)); return d;
}
__device__ __forceinline__ ull mul2(ull a, ull b) {
    ull d; asm("mul.rn.f32x2 %0, %1, %2;" : "=l"(d) : "l"(a), "l"(b)); return d;
}
__device__ __forceinline__ float ex2a(float x) {
    float y; asm("ex2.approx.f32 %0, %1;" : "=f"(y) : "f"(x)); return y;
}
__device__ __forceinline__ float rcpa(float x) {
    float y; asm("rcp.approx.f32 %0, %1;" : "=f"(y) : "f"(x)); return y;
}

// Shapes: b=4, c=16, m=8, h=w=64, O=64.
// CTA: 128 threads = sp(4) x ol(32), covering o-half oh = blockIdx.x&1.
// Full j=16 per thread, NO shuffles (R8 main loop verbatim).
// 3 CTAs resident/SM: cross-CTA overlap of prologue and main loop.
// Smem (floats):
//   qs  [0,8256)       q[i][ol*16+pix], i-stride 516
//   xs  [8256,10368)   x[ch][m*16+pix], ch-stride 132
//   res [10368,10624)  0.125*sum_m x, [i*16+pix]
//   wqs [10624,10880)  wq(this half) * 0.125*log2(e), [ol*8+m]
//   wkp [10880,11456)  ull j-pairs [r2*9+m], rows (2r2,2r2+1), all 64 rows
//   wvp [11456,12032)  same for wv
#define QS_I 516
#define XS_CH 132
#define SMEM_FLOATS 12032
#define SMEM_BYTES (SMEM_FLOATS * 4)

__global__ __launch_bounds__(128, 3) void adapt_attn(
    const float* __restrict__ x,
    const float* __restrict__ wq,
    const float* __restrict__ wk,
    const float* __restrict__ wv,
    float* __restrict__ out)
{
    extern __shared__ __align__(16) float smem[];
    float* qs  = smem;
    float* xs  = smem + 8256;
    float* res = smem + 10368;
    float* wqs = smem + 10624;
    ull*   wkp = (ull*)(smem + 10880);
    ull*   wvp = (ull*)(smem + 11456);

    const int t   = threadIdx.x;
    const int bx  = blockIdx.x;   // 0..15
    const int lwg = bx >> 1;      // 0..7
    const int oh  = bx & 1;       // o-half
    const int lh  = blockIdx.y;   // 0..31
    const int b   = blockIdx.z;   // 0..3
    const int hh0 = 2 * lh, ww0 = 8 * lwg;

    // ---- stage x tile (512 float4, 4 per thread): pix = sp*4 + (hhi*2+col) ----
#pragma unroll
    for (int it = 0; it < 4; ++it) {
        int idx = t + it * 128;
        int q4  = idx & 1;
        int hhi = (idx >> 1) & 1;
        int m   = (idx >> 2) & 7;
        int ch  = idx >> 5;
        const float4 v = *reinterpret_cast<const float4*>(
            x + ((b * 16 + ch) * 8 + m) * 4096 + (hh0 + hhi) * 64 + ww0 + 4 * q4);
        float* dst = xs + ch * XS_CH + m * 16 + 8 * q4 + 2 * hhi;
        *reinterpret_cast<ull*>(dst)     = pk2(v.x, v.y);
        *reinterpret_cast<ull*>(dst + 4) = pk2(v.z, v.w);
    }
    // ---- stage weights (2 entries per thread per table) ----
#pragma unroll
    for (int it = 0; it < 2; ++it) {
        int idx = t + it * 128;             // 0..255
        int m = idx & 7, r = idx >> 3;      // r = 0..31
        wqs[idx] = wq[(oh * 32 + r) * 8 + m] * 0.18033688011112042f; // 0.125*log2e
        wkp[r * 9 + m] = pk2(wk[(2 * r) * 8 + m], wk[(2 * r + 1) * 8 + m]);
        wvp[r * 9 + m] = pk2(wv[(2 * r) * 8 + m], wv[(2 * r + 1) * 8 + m]);
    }
    __syncthreads();

    // ---- res = 0.125 * sum_m x (2 elems per thread) ----
#pragma unroll
    for (int it = 0; it < 2; ++it) {
        int idx = t + it * 128;
        int i = idx >> 4, pix = idx & 15;
        const float* xr = xs + i * XS_CH + pix;
        float s = 0.f;
#pragma unroll
        for (int m = 0; m < 8; ++m) s += xr[m * 16];
        res[i * 16 + pix] = 0.125f * s;
    }

    // ---- cooperative q, loop-interchanged: i = t&15, og = t>>4 -> 4 ol ----
    {
        int i = t & 15, og = t >> 4;        // og 0..7 -> ol = og*4 .. og*4+3
        const ull* xr = reinterpret_cast<const ull*>(xs + i * XS_CH);
        const float* wo = wqs + (og * 4) * 8;
        ull acc[4][8];
#pragma unroll
        for (int n = 0; n < 4; ++n)
#pragma unroll
            for (int p = 0; p < 8; ++p) acc[n][p] = 0ull;
#pragma unroll
        for (int m = 0; m < 8; ++m) {
            ull xm[8];
#pragma unroll
            for (int p = 0; p < 8; ++p) xm[p] = xr[m * 8 + p];
#pragma unroll
            for (int n = 0; n < 4; ++n) {
                ull wb = bc2(wo[n * 8 + m]);
#pragma unroll
                for (int p = 0; p < 8; ++p)
                    acc[n][p] = fma2(wb, xm[p], acc[n][p]);
            }
        }
#pragma unroll
        for (int n = 0; n < 4; ++n) {
            ull* qd = reinterpret_cast<ull*>(qs + i * QS_I + (og * 4 + n) * 16);
#pragma unroll
            for (int p = 0; p < 8; ++p) qd[p] = acc[n][p];
        }
    }

    // ---- per-thread k/v (full j = 16, packed over j-pairs) ----
    const int sp = t & 3;
    const int ol = t >> 2;                 // 0..31
    const int o  = oh * 32 + ol;           // global o
    const int ck = o >> 2;                 // x channel

    ull kq[8][4], vq[8][4];
#pragma unroll
    for (int j2 = 0; j2 < 8; ++j2)
#pragma unroll
        for (int p = 0; p < 4; ++p) { kq[j2][p] = 0ull; vq[j2][p] = 0ull; }
    {
        const ull* wkg = wkp + ((ol & 3) * 8) * 9;
        const ull* wvg = wvp + ((ol & 3) * 8) * 9;
        const float* xck = xs + ck * XS_CH;
#pragma unroll
        for (int m = 0; m < 8; ++m) {
            float4 xv = *reinterpret_cast<const float4*>(xck + m * 16 + sp * 4);
            ull xb0 = bc2(xv.x), xb1 = bc2(xv.y), xb2 = bc2(xv.z), xb3 = bc2(xv.w);
#pragma unroll
            for (int j2 = 0; j2 < 8; ++j2) {
                ull wkv = wkg[j2 * 9 + m];
                kq[j2][0] = fma2(wkv, xb0, kq[j2][0]);
                kq[j2][1] = fma2(wkv, xb1, kq[j2][1]);
                kq[j2][2] = fma2(wkv, xb2, kq[j2][2]);
                kq[j2][3] = fma2(wkv, xb3, kq[j2][3]);
                ull wvv = wvg[j2 * 9 + m];
                vq[j2][0] = fma2(wvv, xb0, vq[j2][0]);
                vq[j2][1] = fma2(wvv, xb1, vq[j2][1]);
                vq[j2][2] = fma2(wvv, xb2, vq[j2][2]);
                vq[j2][3] = fma2(wvv, xb3, vq[j2][3]);
            }
        }
    }
    __syncthreads();   // qs/res complete before main loop

    const float* qso  = qs + ol * 16 + sp * 4;
    const ull*   resp = reinterpret_cast<const ull*>(res) + sp * 2;
    float* op = out + ((b * 16) * 64 + o) * 4096 + hh0 * 64 + ww0 + 2 * sp;

    // ==== main loop (R8 verbatim): q prefetch, no shuffles ====
    float4 qv = *reinterpret_cast<const float4*>(qso);
#pragma unroll 1
    for (int i = 0; i < 16; ++i) {
        float4 qvn = *reinterpret_cast<const float4*>(qso + ((i + 1) & 15) * QS_I);

        ull qb0 = bc2(qv.x), qb1 = bc2(qv.y), qb2 = bc2(qv.z), qb3 = bc2(qv.w);

        // att (pre-scaled) -> e = 2^att packed over j-pairs (no max: |att| << 30)
        ull ep[8];
#pragma unroll
        for (int j2 = 0; j2 < 8; ++j2) {
            ull at = mul2(qb0, kq[j2][0]);
            at = fma2(qb1, kq[j2][1], at);
            at = fma2(qb2, kq[j2][2], at);
            at = fma2(qb3, kq[j2][3], at);
            float alo, ahi; upk2(at, alo, ahi);
            ep[j2] = pk2(ex2a(alo), ex2a(ahi));
        }

        // softmax denominator (packed tree + 1 horizontal)
        ull s = add2(add2(add2(ep[0], ep[1]), add2(ep[2], ep[3])),
                     add2(add2(ep[4], ep[5]), add2(ep[6], ep[7])));
        float slo, shi; upk2(s, slo, shi);
        ull invb = bc2(rcpa(slo + shi));

        // out[p] = horiz( sum_j2 ep[j2] (x) vq[j2][p] )
        ull a0 = mul2(ep[0], vq[0][0]);
        ull a1 = mul2(ep[0], vq[0][1]);
        ull a2 = mul2(ep[0], vq[0][2]);
        ull a3 = mul2(ep[0], vq[0][3]);
#pragma unroll
        for (int j2 = 1; j2 < 8; ++j2) {
            a0 = fma2(ep[j2], vq[j2][0], a0);
            a1 = fma2(ep[j2], vq[j2][1], a1);
            a2 = fma2(ep[j2], vq[j2][2], a2);
            a3 = fma2(ep[j2], vq[j2][3], a3);
        }
        float e0, e1, e2, e3, d0, d1, d2, d3;
        upk2(a0, e0, d0); upk2(a1, e1, d1);
        upk2(a2, e2, d2); upk2(a3, e3, d3);

        ull f0 = fma2(pk2(e0 + d0, e1 + d1), invb, resp[i * 8]);      // row hh0
        ull f1 = fma2(pk2(e2 + d2, e3 + d3), invb, resp[i * 8 + 1]);  // row hh0+1
        *reinterpret_cast<ull*>(op)      = f0;
        *reinterpret_cast<ull*>(op + 64) = f1;
        op += 64 * 4096;

        qv = qvn;
    }
}

extern "C" void kernel_launch(void* const* d_in, const int* in_sizes, int n_in,
                              void* d_out, int out_size) {
    const float* x  = (const float*)d_in[0];
    const float* wq = (const float*)d_in[1];
    const float* wk = (const float*)d_in[2];
    const float* wv = (const float*)d_in[3];
    // d_in[4] (w_p): positional term is constant over the softmax axis -> cancels exactly.
    static int attr_set = 0;
    if (!attr_set) {
        cudaFuncSetAttribute(adapt_attn, cudaFuncAttributeMaxDynamicSharedMemorySize,
                             SMEM_BYTES);
        attr_set = 1;
    }
    dim3 grid(16, 32, 4);   // (lwg*2+oh, lh, b)
    adapt_attn<<<grid, 128, SMEM_BYTES>>>(x, wq, wk, wv, (float*)d_out);
}